// round 1
// baseline (speedup 1.0000x reference)
#include <cuda_runtime.h>
#include <cstdint>

#define N_DATA 131072
#define DVEC   128
#define NSUB   8
#define DSUB   16
#define KCLUS  256
#define NCB    64
#define PPB    256
#define MAXWORK (N_DATA / PPB + NCB)   // 576

typedef unsigned long long u64;

// ---------------- device scratch (static: no allocations allowed) ----------------
__device__ float g_xT[(size_t)N_DATA * DVEC];          // 67 MB  x transposed [n][d]
__device__ float g_ckPack[NCB * NSUB * KCLUS * DSUB];  // 8 MB   codebook [cb][s][k][d]
__device__ float g_cnorm[NCB * NSUB * KCLUS];          // 512 KB centroid norms
__device__ float g_selnorm[NCB];
__device__ float4 g_selPack[64 * 32];                  // selector centroids, f32x2-pair layout
__device__ int   g_labels[N_DATA];
__device__ int   g_perm[N_DATA];
__device__ u64   g_codes[N_DATA];
__device__ int   g_hist[NCB];
__device__ int   g_offsets[NCB + 1];
__device__ int   g_cursor[NCB];
__device__ int4  g_worklist[MAXWORK];
__device__ int   g_nwork;

// ---------------- f32x2 packed-FMA helpers ----------------
__device__ __forceinline__ u64 pk2(float lo, float hi) {
    u64 r; asm("mov.b64 %0, {%1,%2};" : "=l"(r) : "f"(lo), "f"(hi)); return r;
}
__device__ __forceinline__ float hsum2(u64 v) {
    float lo, hi; asm("mov.b64 {%0,%1}, %2;" : "=f"(lo), "=f"(hi) : "l"(v)); return lo + hi;
}
__device__ __forceinline__ u64 ffma2(u64 a, u64 b, u64 c) {
    u64 d; asm("fma.rn.f32x2 %0, %1, %2, %3;" : "=l"(d) : "l"(a), "l"(b), "l"(c)); return d;
}
__device__ __forceinline__ u64 fmul2(u64 a, u64 b) {
    u64 d; asm("mul.rn.f32x2 %0, %1, %2;" : "=l"(d) : "l"(a), "l"(b)); return d;
}

// ---------------- K0: zero per-replay state ----------------
__global__ void k_init() {
    int t = threadIdx.x;
    if (t < NCB) g_hist[t] = 0;
    if (t == 0) g_nwork = 0;
}

// ---------------- K1: pack codebook [cb][s][d][k] -> [cb][s][k][d] + norms; pack selector ----------------
__global__ void k_pack(const float* __restrict__ cb, const float* __restrict__ sel) {
    int bid = blockIdx.x, tid = threadIdx.x;
    if (bid < NCB * NSUB) {
        __shared__ float t[DSUB][KCLUS + 1];
        const float* src = cb + (size_t)bid * DSUB * KCLUS;
        for (int i = tid; i < DSUB * KCLUS; i += 256) t[i >> 8][i & 255] = src[i];
        __syncthreads();
        int k = tid;
        float v[DSUB]; float cn = 0.f;
        #pragma unroll
        for (int d = 0; d < DSUB; d++) { v[d] = t[d][k]; cn = fmaf(v[d], v[d], cn); }
        float4* dst = (float4*)(g_ckPack + ((size_t)bid * KCLUS + k) * DSUB);
        dst[0] = make_float4(v[0], v[1], v[2], v[3]);
        dst[1] = make_float4(v[4], v[5], v[6], v[7]);
        dst[2] = make_float4(v[8], v[9], v[10], v[11]);
        dst[3] = make_float4(v[12], v[13], v[14], v[15]);
        g_cnorm[bid * KCLUS + k] = cn;
    } else {
        if (tid < NCB) {
            float s = 0.f;
            for (int d = 0; d < DVEC; d++) { float v = sel[d * NCB + tid]; s = fmaf(v, v, s); }
            g_selnorm[tid] = s;
        }
        for (int i = tid; i < 64 * 32; i += 256) {
            int dp = i >> 5, l2 = i & 31;
            g_selPack[i] = make_float4(sel[(2 * dp) * NCB + 2 * l2],
                                       sel[(2 * dp + 1) * NCB + 2 * l2],
                                       sel[(2 * dp) * NCB + 2 * l2 + 1],
                                       sel[(2 * dp + 1) * NCB + 2 * l2 + 1]);
        }
    }
}

// ---------------- K2: transpose x [d][n] -> g_xT [n][d] ----------------
__global__ void k_transpose(const float* __restrict__ x) {
    __shared__ float t[32][33];
    int nb = blockIdx.x * 32, db = blockIdx.y * 32;
    int tx = threadIdx.x, ty = threadIdx.y;
    #pragma unroll
    for (int j = 0; j < 4; j++)
        t[ty + 8 * j][tx] = x[(size_t)(db + ty + 8 * j) * N_DATA + nb + tx];
    __syncthreads();
    #pragma unroll
    for (int j = 0; j < 4; j++)
        g_xT[(size_t)(nb + ty + 8 * j) * DVEC + db + tx] = t[tx][ty + 8 * j];
}

// ---------------- K3: labels (argmin over 64 selector centroids, 128-d) ----------------
__global__ void __launch_bounds__(256, 1) k_label(const float* __restrict__ x) {
    __shared__ float4 selS[64 * 32];
    __shared__ float snS[NCB];
    __shared__ int hS[NCB];
    int tid = threadIdx.x;
    for (int i = tid; i < 2048; i += 256) selS[i] = g_selPack[i];
    if (tid < NCB) { snS[tid] = g_selnorm[tid]; hS[tid] = 0; }
    __syncthreads();

    int n = blockIdx.x * 256 + tid;
    const float* xc = x + n;
    u64 acc[NCB];
    #pragma unroll
    for (int l = 0; l < NCB; l++) acc[l] = 0ULL;
    u64 axx = 0ULL;

    #pragma unroll 2
    for (int dp = 0; dp < 64; dp++) {
        float xa = xc[(size_t)(2 * dp) * N_DATA];
        float xb = xc[(size_t)(2 * dp + 1) * N_DATA];
        u64 x2 = pk2(xa, xb);
        axx = ffma2(x2, x2, axx);
        #pragma unroll
        for (int l2 = 0; l2 < 32; l2++) {
            float4 c = selS[dp * 32 + l2];
            acc[2 * l2]     = ffma2(x2, pk2(c.x, c.y), acc[2 * l2]);
            acc[2 * l2 + 1] = ffma2(x2, pk2(c.z, c.w), acc[2 * l2 + 1]);
        }
    }
    float xn = hsum2(axx);
    float best = 3.4e38f; int bl = 0;
    #pragma unroll
    for (int l = 0; l < NCB; l++) {
        float cr = hsum2(acc[l]);
        float d = fmaf(-2.f, cr, xn) + snS[l];
        if (d < best) { best = d; bl = l; }
    }
    g_labels[n] = bl;
    atomicAdd(&hS[bl], 1);
    __syncthreads();
    if (tid < NCB && hS[tid] > 0) atomicAdd(&g_hist[tid], hS[tid]);
}

// ---------------- K4: scan + worklist build (serial, tiny) ----------------
__global__ void k_scan() {
    if (threadIdx.x == 0) {
        int off = 0, nw = 0;
        for (int l = 0; l < NCB; l++) {
            int c = g_hist[l];
            g_offsets[l] = off;
            g_cursor[l] = 0;
            int s = 0;
            while (s < c) {
                int cc = min(PPB, c - s);
                g_worklist[nw] = make_int4(l, off + s, cc, 0);
                nw++; s += PPB;
            }
            off += c;
        }
        g_offsets[NCB] = off;
        g_nwork = nw;
    }
}

// ---------------- K5: scatter points into label-sorted order ----------------
__global__ void k_scatter() {
    int n = blockIdx.x * 256 + threadIdx.x;
    int lab = g_labels[n];
    int pos = atomicAdd(&g_cursor[lab], 1);
    g_perm[g_offsets[lab] + pos] = n;
}

// ---------------- K6: main PQ assignment (heavy kernel) ----------------
__global__ void __launch_bounds__(128) k_main() {
    __shared__ float4 ckS[KCLUS * 4];  // 16 KB: [k][d0..15]
    __shared__ float cnS[KCLUS];
    int bid = blockIdx.x;
    if (bid >= g_nwork) return;
    int4 w = g_worklist[bid];
    int label = w.x, start = w.y, cnt = w.z;
    int tid = threadIdx.x;

    bool v0 = (tid < cnt), v1 = (tid + 128 < cnt);
    int p0 = g_perm[start + (v0 ? tid : 0)];
    int p1 = g_perm[start + (v1 ? tid + 128 : 0)];
    u64 codeA = 0, codeB = 0;

    for (int s = 0; s < NSUB; s++) {
        __syncthreads();
        {
            const float4* src = (const float4*)(g_ckPack + ((size_t)(label * NSUB + s) * KCLUS) * DSUB);
            const float* cns = g_cnorm + (label * NSUB + s) * KCLUS;
            for (int k = tid; k < KCLUS; k += 128) {
                ckS[k * 4 + 0] = src[k * 4 + 0];
                ckS[k * 4 + 1] = src[k * 4 + 1];
                ckS[k * 4 + 2] = src[k * 4 + 2];
                ckS[k * 4 + 3] = src[k * 4 + 3];
                cnS[k] = cns[k];
            }
        }
        __syncthreads();

        const float4* xr0 = (const float4*)(g_xT + (size_t)p0 * DVEC + s * DSUB);
        const float4* xr1 = (const float4*)(g_xT + (size_t)p1 * DVEC + s * DSUB);
        float4 a0 = xr0[0], a1 = xr0[1], a2 = xr0[2], a3 = xr0[3];
        float4 b0 = xr1[0], b1 = xr1[1], b2 = xr1[2], b3 = xr1[3];
        u64 xA[8] = { pk2(a0.x,a0.y), pk2(a0.z,a0.w), pk2(a1.x,a1.y), pk2(a1.z,a1.w),
                      pk2(a2.x,a2.y), pk2(a2.z,a2.w), pk2(a3.x,a3.y), pk2(a3.z,a3.w) };
        u64 xB[8] = { pk2(b0.x,b0.y), pk2(b0.z,b0.w), pk2(b1.x,b1.y), pk2(b1.z,b1.w),
                      pk2(b2.x,b2.y), pk2(b2.z,b2.w), pk2(b3.x,b3.y), pk2(b3.z,b3.w) };

        u64 nA = fmul2(xA[0], xA[0]);
        u64 nB = fmul2(xB[0], xB[0]);
        #pragma unroll
        for (int i = 1; i < 8; i++) { nA = ffma2(xA[i], xA[i], nA); nB = ffma2(xB[i], xB[i], nB); }
        float xnA = hsum2(nA), xnB = hsum2(nB);

        float bestA = 3.4e38f, bestB = 3.4e38f;
        int bkA = 0, bkB = 0;
        #pragma unroll 2
        for (int k = 0; k < KCLUS; k++) {
            float4 c0 = ckS[k * 4 + 0], c1 = ckS[k * 4 + 1], c2 = ckS[k * 4 + 2], c3 = ckS[k * 4 + 3];
            u64 p0v = pk2(c0.x, c0.y), p1v = pk2(c0.z, c0.w), p2v = pk2(c1.x, c1.y), p3v = pk2(c1.z, c1.w);
            u64 p4v = pk2(c2.x, c2.y), p5v = pk2(c2.z, c2.w), p6v = pk2(c3.x, c3.y), p7v = pk2(c3.z, c3.w);
            float cn = cnS[k];

            u64 sA = fmul2(xA[0], p0v);
            sA = ffma2(xA[1], p1v, sA); sA = ffma2(xA[2], p2v, sA); sA = ffma2(xA[3], p3v, sA);
            sA = ffma2(xA[4], p4v, sA); sA = ffma2(xA[5], p5v, sA); sA = ffma2(xA[6], p6v, sA);
            sA = ffma2(xA[7], p7v, sA);
            float dA = fmaf(-2.f, hsum2(sA), xnA) + cn;
            if (dA < bestA) { bestA = dA; bkA = k; }

            u64 sB = fmul2(xB[0], p0v);
            sB = ffma2(xB[1], p1v, sB); sB = ffma2(xB[2], p2v, sB); sB = ffma2(xB[3], p3v, sB);
            sB = ffma2(xB[4], p4v, sB); sB = ffma2(xB[5], p5v, sB); sB = ffma2(xB[6], p6v, sB);
            sB = ffma2(xB[7], p7v, sB);
            float dB = fmaf(-2.f, hsum2(sB), xnB) + cn;
            if (dB < bestB) { bestB = dB; bkB = k; }
        }
        codeA |= ((u64)bkA) << (8 * s);
        codeB |= ((u64)bkB) << (8 * s);
    }
    if (v0) g_codes[p0] = codeA;
    if (v1) g_codes[p1] = codeB;
}

// ---------------- K7: decode, n-coalesced output writes ----------------
__global__ void k_decode(float* __restrict__ out) {
    int n = blockIdx.x * 256 + threadIdx.x;
    int lab = g_labels[n];
    u64 code = g_codes[n];
    #pragma unroll
    for (int s = 0; s < NSUB; s++) {
        int k = (int)((code >> (8 * s)) & 255ULL);
        const float4* src = (const float4*)(g_ckPack + ((size_t)(lab * NSUB + s) * KCLUS + k) * DSUB);
        float4 vv[4] = { src[0], src[1], src[2], src[3] };
        size_t b = (size_t)(s * DSUB) * N_DATA + n;
        #pragma unroll
        for (int j = 0; j < 4; j++) {
            out[b + (size_t)(4 * j + 0) * N_DATA] = vv[j].x;
            out[b + (size_t)(4 * j + 1) * N_DATA] = vv[j].y;
            out[b + (size_t)(4 * j + 2) * N_DATA] = vv[j].z;
            out[b + (size_t)(4 * j + 3) * N_DATA] = vv[j].w;
        }
    }
}

// ---------------- launch ----------------
extern "C" void kernel_launch(void* const* d_in, const int* in_sizes, int n_in,
                              void* d_out, int out_size) {
    const float* x   = (const float*)d_in[0];
    const float* cb  = (const float*)d_in[1];
    const float* sel = (const float*)d_in[2];
    float* out = (float*)d_out;

    k_init<<<1, 64>>>();
    k_pack<<<NCB * NSUB + 1, 256>>>(cb, sel);
    dim3 tb(32, 8), tg(N_DATA / 32, DVEC / 32);
    k_transpose<<<tg, tb>>>(x);
    k_label<<<N_DATA / 256, 256>>>(x);
    k_scan<<<1, 32>>>();
    k_scatter<<<N_DATA / 256, 256>>>();
    k_main<<<MAXWORK, 128>>>();
    k_decode<<<N_DATA / 256, 256>>>(out);
}

// round 2
// speedup vs baseline: 1.0674x; 1.0674x over previous
#include <cuda_runtime.h>
#include <cstdint>

#define N_DATA 131072
#define DVEC   128
#define NSUB   8
#define DSUB   16
#define KCLUS  256
#define NCB    64
#define PPB    256
#define MAXWORK (N_DATA / PPB + NCB)   // 576

#define EPS_M  1e-3f   // k_main refine trigger (score units)
#define EPS_L  5e-3f   // k_label refine trigger

typedef unsigned long long u64;

// ---------------- device scratch (static: no allocations allowed) ----------------
__device__ float g_xT[(size_t)N_DATA * DVEC];                       // 67 MB x transposed [n][d]
__device__ float g_ckPack[NCB * NSUB * KCLUS * DSUB];               // 8 MB [cb][s][k][d] (decode+refine)
__device__ __align__(16) u64 g_ckPair[(size_t)NCB * NSUB * 128 * DSUB]; // 8 MB pair-packed [cb*s][p][d]
__device__ __align__(16) u64 g_cn2[NCB * NSUB * 128];               // (-cn(2p)/2, -cn(2p+1)/2)
__device__ __align__(16) u64 g_selPair[64 * 32 * 2];                // [dstep][pair][2dims]
__device__ u64   g_ln2[32];
__device__ int   g_labels[N_DATA];
__device__ int   g_perm[N_DATA];
__device__ u64   g_codes[N_DATA];
__device__ int   g_hist[NCB];
__device__ int   g_offsets[NCB + 1];
__device__ int   g_cursor[NCB];
__device__ int4  g_worklist[MAXWORK];
__device__ int   g_nwork;

// ---------------- f32x2 helpers ----------------
__device__ __forceinline__ u64 pk2(float lo, float hi) {
    u64 r; asm("mov.b64 %0, {%1,%2};" : "=l"(r) : "f"(lo), "f"(hi)); return r;
}
__device__ __forceinline__ void unpk2(u64 v, float& lo, float& hi) {
    asm("mov.b64 {%0,%1}, %2;" : "=f"(lo), "=f"(hi) : "l"(v));
}
__device__ __forceinline__ u64 ffma2(u64 a, u64 b, u64 c) {
    u64 d; asm("fma.rn.f32x2 %0, %1, %2, %3;" : "=l"(d) : "l"(a), "l"(b), "l"(c)); return d;
}
// branchless top-2 (max) with first-index tie-break (strict >)
__device__ __forceinline__ void top2(float s, int k, float& b1, int& i1, float& b2, int& i2) {
    bool g1 = s > b1;
    bool g2 = s > b2;
    float nb2 = g1 ? b1 : (g2 ? s : b2);
    int   ni2 = g1 ? i1 : (g2 ? k : i2);
    b1 = g1 ? s : b1;
    i1 = g1 ? k : i1;
    b2 = nb2; i2 = ni2;
}

// ---------------- K0: zero per-replay state ----------------
__global__ void k_init() {
    int t = threadIdx.x;
    if (t < NCB) g_hist[t] = 0;
}

// ---------------- K1: pack codebook + selector ----------------
__global__ void k_pack(const float* __restrict__ cb, const float* __restrict__ sel) {
    int bid = blockIdx.x, tid = threadIdx.x;
    if (bid < NCB * NSUB) {
        __shared__ float t[DSUB][KCLUS + 1];
        __shared__ float cnsh[KCLUS];
        const float* src = cb + (size_t)bid * DSUB * KCLUS;
        for (int i = tid; i < DSUB * KCLUS; i += 256) t[i >> 8][i & 255] = src[i];
        __syncthreads();
        int k = tid;
        float v[DSUB]; float cn = 0.f;
        #pragma unroll
        for (int d = 0; d < DSUB; d++) { v[d] = t[d][k]; cn = fmaf(v[d], v[d], cn); }
        // keep [k][d] float layout for decode + fp64 refine
        float4* dst = (float4*)(g_ckPack + ((size_t)bid * KCLUS + k) * DSUB);
        dst[0] = make_float4(v[0], v[1], v[2], v[3]);
        dst[1] = make_float4(v[4], v[5], v[6], v[7]);
        dst[2] = make_float4(v[8], v[9], v[10], v[11]);
        dst[3] = make_float4(v[12], v[13], v[14], v[15]);
        cnsh[k] = cn;
        __syncthreads();
        if (tid < 128) {
            int p = tid;
            g_cn2[bid * 128 + p] = pk2(-0.5f * cnsh[2 * p], -0.5f * cnsh[2 * p + 1]);
            u64* dp = g_ckPair + ((size_t)bid * 128 + p) * DSUB;
            #pragma unroll
            for (int d = 0; d < DSUB; d++)
                dp[d] = pk2(t[d][2 * p], t[d][2 * p + 1]);
        }
    } else {
        __shared__ float cnselS[NCB];
        if (tid < NCB) {
            float s = 0.f;
            for (int d = 0; d < DVEC; d++) { float v = sel[d * NCB + tid]; s = fmaf(v, v, s); }
            cnselS[tid] = s;
        }
        __syncthreads();
        if (tid < 32) g_ln2[tid] = pk2(-0.5f * cnselS[2 * tid], -0.5f * cnselS[2 * tid + 1]);
        // g_selPair[ds*64 + p*2 + j] = (sel[(2ds+j)][2p], sel[(2ds+j)][2p+1])
        for (int i = tid; i < 64 * 32 * 2; i += 256) {
            int ds = i >> 6, r = i & 63, p = r >> 1, j = r & 1, d = 2 * ds + j;
            g_selPair[i] = pk2(sel[d * NCB + 2 * p], sel[d * NCB + 2 * p + 1]);
        }
    }
}

// ---------------- K2: transpose x [d][n] -> g_xT [n][d] ----------------
__global__ void k_transpose(const float* __restrict__ x) {
    __shared__ float t[32][33];
    int nb = blockIdx.x * 32, db = blockIdx.y * 32;
    int tx = threadIdx.x, ty = threadIdx.y;
    #pragma unroll
    for (int j = 0; j < 4; j++)
        t[ty + 8 * j][tx] = x[(size_t)(db + ty + 8 * j) * N_DATA + nb + tx];
    __syncthreads();
    #pragma unroll
    for (int j = 0; j < 4; j++)
        g_xT[(size_t)(nb + ty + 8 * j) * DVEC + db + tx] = t[tx][ty + 8 * j];
}

// ---------------- K3: labels (argmax of cross - cn/2 over 64 centroids) ----------------
__global__ void __launch_bounds__(256, 2) k_label(const float* __restrict__ x,
                                                  const float* __restrict__ sel) {
    __shared__ __align__(16) u64 selS[64 * 32 * 2];  // 32 KB
    __shared__ u64 ln2S[32];
    __shared__ int hS[NCB];
    int tid = threadIdx.x;
    for (int i = tid; i < 2048; i += 256)
        ((ulonglong2*)selS)[i] = ((const ulonglong2*)g_selPair)[i];
    if (tid < 32) ln2S[tid] = g_ln2[tid];
    if (tid < NCB) hS[tid] = 0;
    __syncthreads();

    int n = blockIdx.x * 256 + tid;
    const float* xc = x + n;

    u64 acc[32];
    #pragma unroll
    for (int p = 0; p < 32; p++) acc[p] = ln2S[p];

    #pragma unroll 2
    for (int ds = 0; ds < 64; ds++) {
        float x0 = xc[(size_t)(2 * ds) * N_DATA];
        float x1 = xc[(size_t)(2 * ds + 1) * N_DATA];
        u64 xd0 = pk2(x0, x0), xd1 = pk2(x1, x1);
        const ulonglong2* row = (const ulonglong2*)(selS + ds * 64);
        #pragma unroll
        for (int p = 0; p < 32; p++) {
            ulonglong2 c = row[p];
            acc[p] = ffma2(xd0, c.x, acc[p]);
            acc[p] = ffma2(xd1, c.y, acc[p]);
        }
    }

    float b1 = -3.4e38f, b2 = -3.4e38f; int i1 = 0, i2 = 0;
    #pragma unroll
    for (int p = 0; p < 32; p++) {
        float lo, hi; unpk2(acc[p], lo, hi);
        top2(lo, 2 * p,     b1, i1, b2, i2);
        top2(hi, 2 * p + 1, b1, i1, b2, i2);
    }

    if (b1 - b2 < EPS_L) {   // fp64 refine of the two candidates
        double d1 = 0.0, d2 = 0.0;
        for (int d = 0; d < DVEC; d++) {
            double xv = (double)xc[(size_t)d * N_DATA];
            double t1 = xv - (double)sel[d * NCB + i1];
            double t2 = xv - (double)sel[d * NCB + i2];
            d1 = fma(t1, t1, d1);
            d2 = fma(t2, t2, d2);
        }
        if (d2 < d1 || (d2 == d1 && i2 < i1)) i1 = i2;
    }

    g_labels[n] = i1;
    atomicAdd(&hS[i1], 1);
    __syncthreads();
    if (tid < NCB && hS[tid] > 0) atomicAdd(&g_hist[tid], hS[tid]);
}

// ---------------- K4: scan + worklist build (serial, tiny) ----------------
__global__ void k_scan() {
    if (threadIdx.x == 0) {
        int off = 0, nw = 0;
        for (int l = 0; l < NCB; l++) {
            int c = g_hist[l];
            g_offsets[l] = off;
            g_cursor[l] = 0;
            int s = 0;
            while (s < c) {
                int cc = min(PPB, c - s);
                g_worklist[nw] = make_int4(l, off + s, cc, 0);
                nw++; s += PPB;
            }
            off += c;
        }
        g_offsets[NCB] = off;
        g_nwork = nw;
    }
}

// ---------------- K5: scatter points into label-sorted order ----------------
__global__ void k_scatter() {
    int n = blockIdx.x * 256 + threadIdx.x;
    int lab = g_labels[n];
    int pos = atomicAdd(&g_cursor[lab], 1);
    g_perm[g_offsets[lab] + pos] = n;
}

// ---------------- K6: main PQ assignment ----------------
__global__ void __launch_bounds__(128, 3) k_main() {
    __shared__ __align__(16) u64 ckS[128 * DSUB];  // 16 KB pair-packed tile
    __shared__ u64 cn2S[128];
    int bid = blockIdx.x;
    if (bid >= g_nwork) return;
    int4 w = g_worklist[bid];
    int label = w.x, start = w.y, cnt = w.z;
    int tid = threadIdx.x;

    bool v0 = (tid < cnt), v1 = (tid + 128 < cnt);
    int p0 = g_perm[start + (v0 ? tid : 0)];
    int p1 = g_perm[start + (v1 ? tid + 128 : 0)];
    u64 codeA = 0, codeB = 0;

    for (int s = 0; s < NSUB; s++) {
        __syncthreads();
        {
            const ulonglong2* src = (const ulonglong2*)(g_ckPair + ((size_t)(label * NSUB + s)) * 128 * DSUB);
            ulonglong2* dst = (ulonglong2*)ckS;
            #pragma unroll
            for (int i = 0; i < 8; i++) dst[tid + 128 * i] = src[tid + 128 * i];
            cn2S[tid] = g_cn2[(label * NSUB + s) * 128 + tid];
        }
        __syncthreads();

        const float4* xr0 = (const float4*)(g_xT + (size_t)p0 * DVEC + s * DSUB);
        const float4* xr1 = (const float4*)(g_xT + (size_t)p1 * DVEC + s * DSUB);
        u64 xA[16], xB[16];
        #pragma unroll
        for (int j = 0; j < 4; j++) {
            float4 a = xr0[j], b = xr1[j];
            xA[4 * j + 0] = pk2(a.x, a.x); xA[4 * j + 1] = pk2(a.y, a.y);
            xA[4 * j + 2] = pk2(a.z, a.z); xA[4 * j + 3] = pk2(a.w, a.w);
            xB[4 * j + 0] = pk2(b.x, b.x); xB[4 * j + 1] = pk2(b.y, b.y);
            xB[4 * j + 2] = pk2(b.z, b.z); xB[4 * j + 3] = pk2(b.w, b.w);
        }

        float b1A = -3.4e38f, b2A = -3.4e38f; int k1A = 0, k2A = 0;
        float b1B = -3.4e38f, b2B = -3.4e38f; int k1B = 0, k2B = 0;

        #pragma unroll 2
        for (int p = 0; p < 128; p++) {
            const ulonglong2* cr = (const ulonglong2*)(ckS + p * DSUB);
            ulonglong2 q0 = cr[0], q1 = cr[1], q2 = cr[2], q3 = cr[3];
            ulonglong2 q4 = cr[4], q5 = cr[5], q6 = cr[6], q7 = cr[7];
            u64 c[16] = { q0.x,q0.y,q1.x,q1.y,q2.x,q2.y,q3.x,q3.y,
                          q4.x,q4.y,q5.x,q5.y,q6.x,q6.y,q7.x,q7.y };
            u64 cn2 = cn2S[p];
            u64 aA = cn2, aB = cn2;
            #pragma unroll
            for (int d = 0; d < 16; d++) {
                aA = ffma2(xA[d], c[d], aA);
                aB = ffma2(xB[d], c[d], aB);
            }
            float sA0, sA1, sB0, sB1;
            unpk2(aA, sA0, sA1); unpk2(aB, sB0, sB1);
            top2(sA0, 2 * p,     b1A, k1A, b2A, k2A);
            top2(sA1, 2 * p + 1, b1A, k1A, b2A, k2A);
            top2(sB0, 2 * p,     b1B, k1B, b2B, k2B);
            top2(sB1, 2 * p + 1, b1B, k1B, b2B, k2B);
        }

        // fp64 refine of near-ties (rare)
        if (b1A - b2A < EPS_M) {
            const float* c1 = g_ckPack + ((size_t)(label * NSUB + s) * KCLUS + k1A) * DSUB;
            const float* c2 = g_ckPack + ((size_t)(label * NSUB + s) * KCLUS + k2A) * DSUB;
            const float* xr = g_xT + (size_t)p0 * DVEC + s * DSUB;
            double d1 = 0.0, d2 = 0.0;
            #pragma unroll
            for (int d = 0; d < DSUB; d++) {
                double xv = (double)xr[d];
                double t1 = xv - (double)c1[d], t2 = xv - (double)c2[d];
                d1 = fma(t1, t1, d1); d2 = fma(t2, t2, d2);
            }
            if (d2 < d1 || (d2 == d1 && k2A < k1A)) k1A = k2A;
        }
        if (b1B - b2B < EPS_M) {
            const float* c1 = g_ckPack + ((size_t)(label * NSUB + s) * KCLUS + k1B) * DSUB;
            const float* c2 = g_ckPack + ((size_t)(label * NSUB + s) * KCLUS + k2B) * DSUB;
            const float* xr = g_xT + (size_t)p1 * DVEC + s * DSUB;
            double d1 = 0.0, d2 = 0.0;
            #pragma unroll
            for (int d = 0; d < DSUB; d++) {
                double xv = (double)xr[d];
                double t1 = xv - (double)c1[d], t2 = xv - (double)c2[d];
                d1 = fma(t1, t1, d1); d2 = fma(t2, t2, d2);
            }
            if (d2 < d1 || (d2 == d1 && k2B < k1B)) k1B = k2B;
        }

        codeA |= ((u64)k1A) << (8 * s);
        codeB |= ((u64)k1B) << (8 * s);
    }
    if (v0) g_codes[p0] = codeA;
    if (v1) g_codes[p1] = codeB;
}

// ---------------- K7: decode, n-coalesced output writes ----------------
__global__ void k_decode(float* __restrict__ out) {
    int n = blockIdx.x * 256 + threadIdx.x;
    int lab = g_labels[n];
    u64 code = g_codes[n];
    #pragma unroll
    for (int s = 0; s < NSUB; s++) {
        int k = (int)((code >> (8 * s)) & 255ULL);
        const float4* src = (const float4*)(g_ckPack + ((size_t)(lab * NSUB + s) * KCLUS + k) * DSUB);
        float4 vv[4] = { src[0], src[1], src[2], src[3] };
        size_t b = (size_t)(s * DSUB) * N_DATA + n;
        #pragma unroll
        for (int j = 0; j < 4; j++) {
            out[b + (size_t)(4 * j + 0) * N_DATA] = vv[j].x;
            out[b + (size_t)(4 * j + 1) * N_DATA] = vv[j].y;
            out[b + (size_t)(4 * j + 2) * N_DATA] = vv[j].z;
            out[b + (size_t)(4 * j + 3) * N_DATA] = vv[j].w;
        }
    }
}

// ---------------- launch ----------------
extern "C" void kernel_launch(void* const* d_in, const int* in_sizes, int n_in,
                              void* d_out, int out_size) {
    const float* x   = (const float*)d_in[0];
    const float* cb  = (const float*)d_in[1];
    const float* sel = (const float*)d_in[2];
    float* out = (float*)d_out;

    k_init<<<1, 64>>>();
    k_pack<<<NCB * NSUB + 1, 256>>>(cb, sel);
    dim3 tb(32, 8), tg(N_DATA / 32, DVEC / 32);
    k_transpose<<<tg, tb>>>(x);
    k_label<<<N_DATA / 256, 256>>>(x, sel);
    k_scan<<<1, 32>>>();
    k_scatter<<<N_DATA / 256, 256>>>();
    k_main<<<MAXWORK, 128>>>();
    k_decode<<<N_DATA / 256, 256>>>(out);
}

// round 3
// speedup vs baseline: 1.2872x; 1.2059x over previous
#include <cuda_runtime.h>
#include <cstdint>

#define N_DATA 131072
#define DVEC   128
#define NSUB   8
#define DSUB   16
#define KCLUS  256
#define NCB    64
#define PPB    256
#define MAXWORK (N_DATA / PPB + NCB)   // 576

typedef unsigned long long u64;

// ---------------- device scratch ----------------
__device__ float g_xT[(size_t)N_DATA * DVEC];                       // 67 MB x transposed [n][d]
__device__ float g_ckPack[NCB * NSUB * KCLUS * DSUB];               // 8 MB [cb][s][k][d] (decode)
__device__ __align__(16) u64 g_ckPair[(size_t)NCB * NSUB * 128 * DSUB]; // 8 MB pair-packed
__device__ __align__(16) u64 g_cn2[NCB * NSUB * 128];               // (-cn(2p)/2, -cn(2p+1)/2)
__device__ __align__(16) u64 g_selPair[64 * 32 * 2];                // [dstep][pair][2dims]
__device__ u64   g_ln2[32];
__device__ int   g_labels[N_DATA];
__device__ int   g_perm[N_DATA];
__device__ u64   g_codes[N_DATA];
__device__ int   g_hist[NCB];
__device__ int   g_offsets[NCB + 1];
__device__ int   g_cursor[NCB];
__device__ int4  g_worklist[MAXWORK];
__device__ int   g_nwork;

// ---------------- f32x2 helpers ----------------
__device__ __forceinline__ u64 pk2(float lo, float hi) {
    u64 r; asm("mov.b64 %0, {%1,%2};" : "=l"(r) : "f"(lo), "f"(hi)); return r;
}
__device__ __forceinline__ void unpk2(u64 v, float& lo, float& hi) {
    asm("mov.b64 {%0,%1}, %2;" : "=f"(lo), "=f"(hi) : "l"(v));
}
__device__ __forceinline__ u64 ffma2(u64 a, u64 b, u64 c) {
    u64 d; asm("fma.rn.f32x2 %0, %1, %2, %3;" : "=l"(d) : "l"(a), "l"(b), "l"(c)); return d;
}

// ---------------- K0 ----------------
__global__ void k_init() {
    int t = threadIdx.x;
    if (t < NCB) g_hist[t] = 0;
}

// ---------------- K1: pack codebook + selector ----------------
__global__ void k_pack(const float* __restrict__ cb, const float* __restrict__ sel) {
    int bid = blockIdx.x, tid = threadIdx.x;
    if (bid < NCB * NSUB) {
        __shared__ float t[DSUB][KCLUS + 1];
        __shared__ float cnsh[KCLUS];
        const float* src = cb + (size_t)bid * DSUB * KCLUS;
        for (int i = tid; i < DSUB * KCLUS; i += 256) t[i >> 8][i & 255] = src[i];
        __syncthreads();
        int k = tid;
        float v[DSUB]; float cn = 0.f;
        #pragma unroll
        for (int d = 0; d < DSUB; d++) { v[d] = t[d][k]; cn = fmaf(v[d], v[d], cn); }
        float4* dst = (float4*)(g_ckPack + ((size_t)bid * KCLUS + k) * DSUB);
        dst[0] = make_float4(v[0], v[1], v[2], v[3]);
        dst[1] = make_float4(v[4], v[5], v[6], v[7]);
        dst[2] = make_float4(v[8], v[9], v[10], v[11]);
        dst[3] = make_float4(v[12], v[13], v[14], v[15]);
        cnsh[k] = cn;
        __syncthreads();
        if (tid < 128) {
            int p = tid;
            g_cn2[bid * 128 + p] = pk2(-0.5f * cnsh[2 * p], -0.5f * cnsh[2 * p + 1]);
            u64* dp = g_ckPair + ((size_t)bid * 128 + p) * DSUB;
            #pragma unroll
            for (int d = 0; d < DSUB; d++)
                dp[d] = pk2(t[d][2 * p], t[d][2 * p + 1]);
        }
    } else {
        __shared__ float cnselS[NCB];
        if (tid < NCB) {
            float s = 0.f;
            for (int d = 0; d < DVEC; d++) { float v = sel[d * NCB + tid]; s = fmaf(v, v, s); }
            cnselS[tid] = s;
        }
        __syncthreads();
        if (tid < 32) g_ln2[tid] = pk2(-0.5f * cnselS[2 * tid], -0.5f * cnselS[2 * tid + 1]);
        for (int i = tid; i < 64 * 32 * 2; i += 256) {
            int ds = i >> 6, r = i & 63, p = r >> 1, j = r & 1, d = 2 * ds + j;
            g_selPair[i] = pk2(sel[d * NCB + 2 * p], sel[d * NCB + 2 * p + 1]);
        }
    }
}

// ---------------- K2: transpose x [d][n] -> g_xT [n][d] ----------------
__global__ void k_transpose(const float* __restrict__ x) {
    __shared__ float t[32][33];
    int nb = blockIdx.x * 32, db = blockIdx.y * 32;
    int tx = threadIdx.x, ty = threadIdx.y;
    #pragma unroll
    for (int j = 0; j < 4; j++)
        t[ty + 8 * j][tx] = x[(size_t)(db + ty + 8 * j) * N_DATA + nb + tx];
    __syncthreads();
    #pragma unroll
    for (int j = 0; j < 4; j++)
        g_xT[(size_t)(nb + ty + 8 * j) * DVEC + db + tx] = t[tx][ty + 8 * j];
}

// ---------------- K3: labels ----------------
// argmax of (x . c - ||c||^2/2); x loaded in register-batched chunks of 16 dims
// so 16 coalesced LDGs are in flight per step (DRAM latency hiding).
__global__ void __launch_bounds__(256, 2) k_label(const float* __restrict__ x) {
    __shared__ __align__(16) u64 selS[64 * 32 * 2];  // 32 KB
    __shared__ u64 ln2S[32];
    __shared__ int hS[NCB];
    int tid = threadIdx.x;
    for (int i = tid; i < 2048; i += 256)
        ((ulonglong2*)selS)[i] = ((const ulonglong2*)g_selPair)[i];
    if (tid < 32) ln2S[tid] = g_ln2[tid];
    if (tid < NCB) hS[tid] = 0;
    __syncthreads();

    int n = blockIdx.x * 256 + tid;
    const float* xc = x + n;

    u64 acc[32];
    #pragma unroll
    for (int p = 0; p < 32; p++) acc[p] = ln2S[p];

    for (int c = 0; c < 8; c++) {                     // 8 chunks x 16 dims
        float xr[16];
        const float* xp = xc + (size_t)(16 * c) * N_DATA;
        #pragma unroll
        for (int i = 0; i < 16; i++) xr[i] = xp[(size_t)i * N_DATA];  // batched, MLP=16
        #pragma unroll
        for (int i2 = 0; i2 < 8; i2++) {
            int ds = 8 * c + i2;
            u64 xd0 = pk2(xr[2 * i2], xr[2 * i2]);
            u64 xd1 = pk2(xr[2 * i2 + 1], xr[2 * i2 + 1]);
            const ulonglong2* row = (const ulonglong2*)(selS + ds * 64);
            #pragma unroll
            for (int p = 0; p < 32; p++) {
                ulonglong2 cc = row[p];
                acc[p] = ffma2(xd0, cc.x, acc[p]);
                acc[p] = ffma2(xd1, cc.y, acc[p]);
            }
        }
    }

    float best = -3.4e38f; int bl = 0;
    #pragma unroll
    for (int p = 0; p < 32; p++) {
        float lo, hi; unpk2(acc[p], lo, hi);
        if (lo > best) { best = lo; bl = 2 * p; }
        if (hi > best) { best = hi; bl = 2 * p + 1; }
    }

    g_labels[n] = bl;
    atomicAdd(&hS[bl], 1);
    __syncthreads();
    if (tid < NCB && hS[tid] > 0) atomicAdd(&g_hist[tid], hS[tid]);
}

// ---------------- K4: scan + worklist ----------------
__global__ void k_scan() {
    if (threadIdx.x == 0) {
        int off = 0, nw = 0;
        for (int l = 0; l < NCB; l++) {
            int c = g_hist[l];
            g_offsets[l] = off;
            g_cursor[l] = 0;
            int s = 0;
            while (s < c) {
                int cc = min(PPB, c - s);
                g_worklist[nw] = make_int4(l, off + s, cc, 0);
                nw++; s += PPB;
            }
            off += c;
        }
        g_offsets[NCB] = off;
        g_nwork = nw;
    }
}

// ---------------- K5: scatter ----------------
__global__ void k_scatter() {
    int n = blockIdx.x * 256 + threadIdx.x;
    int lab = g_labels[n];
    int pos = atomicAdd(&g_cursor[lab], 1);
    g_perm[g_offsets[lab] + pos] = n;
}

// ---------------- K6: main PQ assignment ----------------
__global__ void __launch_bounds__(128, 3) k_main() {
    __shared__ __align__(16) u64 ckS[128 * DSUB];  // 16 KB pair-packed tile
    __shared__ u64 cn2S[128];
    int bid = blockIdx.x;
    if (bid >= g_nwork) return;
    int4 w = g_worklist[bid];
    int label = w.x, start = w.y, cnt = w.z;
    int tid = threadIdx.x;

    bool v0 = (tid < cnt), v1 = (tid + 128 < cnt);
    int p0 = g_perm[start + (v0 ? tid : 0)];
    int p1 = g_perm[start + (v1 ? tid + 128 : 0)];
    u64 codeA = 0, codeB = 0;

    for (int s = 0; s < NSUB; s++) {
        // x loads for this s issued before barriers -> latency overlapped with tile load
        const float4* xr0 = (const float4*)(g_xT + (size_t)p0 * DVEC + s * DSUB);
        const float4* xr1 = (const float4*)(g_xT + (size_t)p1 * DVEC + s * DSUB);
        float4 a0 = xr0[0], a1 = xr0[1], a2 = xr0[2], a3 = xr0[3];
        float4 b0 = xr1[0], b1 = xr1[1], b2 = xr1[2], b3 = xr1[3];

        __syncthreads();
        {
            const ulonglong2* src = (const ulonglong2*)(g_ckPair + ((size_t)(label * NSUB + s)) * 128 * DSUB);
            ulonglong2* dst = (ulonglong2*)ckS;
            #pragma unroll
            for (int i = 0; i < 8; i++) dst[tid + 128 * i] = src[tid + 128 * i];
            cn2S[tid] = g_cn2[(label * NSUB + s) * 128 + tid];
        }
        __syncthreads();

        u64 xA[16], xB[16];
        {
            float av[16] = { a0.x,a0.y,a0.z,a0.w, a1.x,a1.y,a1.z,a1.w,
                             a2.x,a2.y,a2.z,a2.w, a3.x,a3.y,a3.z,a3.w };
            float bv[16] = { b0.x,b0.y,b0.z,b0.w, b1.x,b1.y,b1.z,b1.w,
                             b2.x,b2.y,b2.z,b2.w, b3.x,b3.y,b3.z,b3.w };
            #pragma unroll
            for (int d = 0; d < 16; d++) { xA[d] = pk2(av[d], av[d]); xB[d] = pk2(bv[d], bv[d]); }
        }

        float bestA = -3.4e38f, bestB = -3.4e38f;
        int kA = 0, kB = 0;

        #pragma unroll 2
        for (int p = 0; p < 128; p++) {
            const ulonglong2* cr = (const ulonglong2*)(ckS + p * DSUB);
            u64 cn2 = cn2S[p];
            // first half (d0..d7): only 4 ulonglong2 live at a time
            ulonglong2 q0 = cr[0], q1 = cr[1], q2 = cr[2], q3 = cr[3];
            u64 aA = ffma2(xA[0], q0.x, cn2);
            u64 aB = ffma2(xB[0], q0.x, cn2);
            aA = ffma2(xA[1], q0.y, aA);  aB = ffma2(xB[1], q0.y, aB);
            aA = ffma2(xA[2], q1.x, aA);  aB = ffma2(xB[2], q1.x, aB);
            aA = ffma2(xA[3], q1.y, aA);  aB = ffma2(xB[3], q1.y, aB);
            aA = ffma2(xA[4], q2.x, aA);  aB = ffma2(xB[4], q2.x, aB);
            aA = ffma2(xA[5], q2.y, aA);  aB = ffma2(xB[5], q2.y, aB);
            aA = ffma2(xA[6], q3.x, aA);  aB = ffma2(xB[6], q3.x, aB);
            aA = ffma2(xA[7], q3.y, aA);  aB = ffma2(xB[7], q3.y, aB);
            // second half (d8..d15)
            ulonglong2 q4 = cr[4], q5 = cr[5], q6 = cr[6], q7 = cr[7];
            aA = ffma2(xA[8],  q4.x, aA);  aB = ffma2(xB[8],  q4.x, aB);
            aA = ffma2(xA[9],  q4.y, aA);  aB = ffma2(xB[9],  q4.y, aB);
            aA = ffma2(xA[10], q5.x, aA);  aB = ffma2(xB[10], q5.x, aB);
            aA = ffma2(xA[11], q5.y, aA);  aB = ffma2(xB[11], q5.y, aB);
            aA = ffma2(xA[12], q6.x, aA);  aB = ffma2(xB[12], q6.x, aB);
            aA = ffma2(xA[13], q6.y, aA);  aB = ffma2(xB[13], q6.y, aB);
            aA = ffma2(xA[14], q7.x, aA);  aB = ffma2(xB[14], q7.x, aB);
            aA = ffma2(xA[15], q7.y, aA);  aB = ffma2(xB[15], q7.y, aB);

            float sA0, sA1, sB0, sB1;
            unpk2(aA, sA0, sA1); unpk2(aB, sB0, sB1);
            if (sA0 > bestA) { bestA = sA0; kA = 2 * p; }
            if (sA1 > bestA) { bestA = sA1; kA = 2 * p + 1; }
            if (sB0 > bestB) { bestB = sB0; kB = 2 * p; }
            if (sB1 > bestB) { bestB = sB1; kB = 2 * p + 1; }
        }

        codeA |= ((u64)kA) << (8 * s);
        codeB |= ((u64)kB) << (8 * s);
    }
    if (v0) g_codes[p0] = codeA;
    if (v1) g_codes[p1] = codeB;
}

// ---------------- K7: decode ----------------
__global__ void k_decode(float* __restrict__ out) {
    int n = blockIdx.x * 256 + threadIdx.x;
    int lab = g_labels[n];
    u64 code = g_codes[n];
    #pragma unroll
    for (int s = 0; s < NSUB; s++) {
        int k = (int)((code >> (8 * s)) & 255ULL);
        const float4* src = (const float4*)(g_ckPack + ((size_t)(lab * NSUB + s) * KCLUS + k) * DSUB);
        float4 vv[4] = { src[0], src[1], src[2], src[3] };
        size_t b = (size_t)(s * DSUB) * N_DATA + n;
        #pragma unroll
        for (int j = 0; j < 4; j++) {
            out[b + (size_t)(4 * j + 0) * N_DATA] = vv[j].x;
            out[b + (size_t)(4 * j + 1) * N_DATA] = vv[j].y;
            out[b + (size_t)(4 * j + 2) * N_DATA] = vv[j].z;
            out[b + (size_t)(4 * j + 3) * N_DATA] = vv[j].w;
        }
    }
}

// ---------------- launch ----------------
extern "C" void kernel_launch(void* const* d_in, const int* in_sizes, int n_in,
                              void* d_out, int out_size) {
    const float* x   = (const float*)d_in[0];
    const float* cb  = (const float*)d_in[1];
    const float* sel = (const float*)d_in[2];
    float* out = (float*)d_out;

    k_init<<<1, 64>>>();
    k_pack<<<NCB * NSUB + 1, 256>>>(cb, sel);
    dim3 tb(32, 8), tg(N_DATA / 32, DVEC / 32);
    k_transpose<<<tg, tb>>>(x);
    k_label<<<N_DATA / 256, 256>>>(x);
    k_scan<<<1, 32>>>();
    k_scatter<<<N_DATA / 256, 256>>>();
    k_main<<<MAXWORK, 128>>>();
    k_decode<<<N_DATA / 256, 256>>>(out);
}